// round 13
// baseline (speedup 1.0000x reference)
#include <cuda_runtime.h>
#include <cuda_fp16.h>
#include <cstdint>

// ---------------------------------------------------------------------------
// DLRM forward. GEMMs via mma.sync.m16n8k16.f16, 3-term fp16 split
// (Ah*Bh + Al*Bh + Ah*Bl), fp32 accum (R12 GEMM — at the mma.sync wall).
// R13: interact processes EMBDIM in two 64-col passes -> half smem/warp,
// higher occupancy, same arithmetic.
// ---------------------------------------------------------------------------

#define BATCH   16384
#define NDENSE  13
#define NSPARSE 26
#define XCOLS   39
#define EMBDIM  128
#define VOCAB   1000000
#define NFEAT   27

// -------------------- scratch planes (device globals) ----------------------
__device__ __align__(16) uint16_t g_a0h[BATCH * 32],   g_a0l[BATCH * 32];
__device__ __align__(16) uint16_t g_h1h[BATCH * 512],  g_h1l[BATCH * 512];
__device__ __align__(16) uint16_t g_h2h[BATCH * 256],  g_h2l[BATCH * 256];
__device__ __align__(16) float    g_bot[BATCH * 128];
__device__ __align__(16) uint16_t g_t0h[BATCH * 512],  g_t0l[BATCH * 512];
__device__ __align__(16) uint16_t g_t1h[BATCH * 1024], g_t1l[BATCH * 1024];
__device__ __align__(16) uint16_t g_t2h[BATCH * 1024], g_t2l[BATCH * 1024];
__device__ __align__(16) uint16_t g_t3h[BATCH * 512],  g_t3l[BATCH * 512];
__device__ __align__(16) uint16_t g_t4h[BATCH * 256],  g_t4l[BATCH * 256];
// transposed weight planes [N][Kpad]
__device__ __align__(16) uint16_t g_w0h [512  * 32],   g_w0l [512  * 32];
__device__ __align__(16) uint16_t g_w1h [256  * 512],  g_w1l [256  * 512];
__device__ __align__(16) uint16_t g_w2h [128  * 256],  g_w2l [128  * 256];
__device__ __align__(16) uint16_t g_tw0h[1024 * 512],  g_tw0l[1024 * 512];
__device__ __align__(16) uint16_t g_tw1h[1024 * 1024], g_tw1l[1024 * 1024];
__device__ __align__(16) uint16_t g_tw2h[512  * 1024], g_tw2l[512  * 1024];
__device__ __align__(16) uint16_t g_tw3h[256  * 512],  g_tw3l[256  * 512];

// ---------------------------------------------------------------------------
__device__ __forceinline__ void split_h(float v, uint16_t& h, uint16_t& l) {
    __half hh = __float2half_rn(v);
    __half ll = __float2half_rn(v - __half2float(hh));
    h = __half_as_ushort(hh);
    l = __half_as_ushort(ll);
}

__device__ __forceinline__ void mma16(float* c, const uint32_t* a,
                                      uint32_t b0, uint32_t b1) {
    asm volatile(
        "mma.sync.aligned.m16n8k16.row.col.f32.f16.f16.f32 "
        "{%0,%1,%2,%3}, {%4,%5,%6,%7}, {%8,%9}, {%0,%1,%2,%3};\n"
        : "+f"(c[0]), "+f"(c[1]), "+f"(c[2]), "+f"(c[3])
        : "r"(a[0]), "r"(a[1]), "r"(a[2]), "r"(a[3]), "r"(b0), "r"(b1));
}

__device__ __forceinline__ void ldsm4(uint32_t* r, uint32_t addr) {
    asm volatile(
        "ldmatrix.sync.aligned.m8n8.x4.shared.b16 {%0,%1,%2,%3}, [%4];\n"
        : "=r"(r[0]), "=r"(r[1]), "=r"(r[2]), "=r"(r[3]) : "r"(addr));
}

__device__ __forceinline__ void cpa16(uint32_t dst, const void* src) {
    asm volatile("cp.async.cg.shared.global [%0], [%1], 16;\n"
                 :: "r"(dst), "l"(src));
}

// ---------------------------------------------------------------------------
// Fused prepass: split/transpose ALL weights + input to f16 planes, 1 launch.
// ---------------------------------------------------------------------------
__device__ __forceinline__ void seg_conv(const float* __restrict__ in,
                                         uint16_t* __restrict__ oh,
                                         uint16_t* __restrict__ ol,
                                         int j, int K, int Kpad, int N) {
    int n = j / Kpad, k = j - n * Kpad;
    float v = (k < K) ? in[(size_t)k * N + n] : 0.f;
    split_h(v, oh[j], ol[j]);
}

#define CONV_TOTAL 2932736

__global__ void conv_all(const float* __restrict__ x,
    const float* __restrict__ i0, const float* __restrict__ i1,
    const float* __restrict__ i2, const float* __restrict__ i3,
    const float* __restrict__ i4, const float* __restrict__ i5,
    const float* __restrict__ i6,
    uint16_t* a0h, uint16_t* a0l,
    uint16_t* o0h, uint16_t* o0l, uint16_t* o1h, uint16_t* o1l,
    uint16_t* o2h, uint16_t* o2l, uint16_t* o3h, uint16_t* o3l,
    uint16_t* o4h, uint16_t* o4l, uint16_t* o5h, uint16_t* o5l,
    uint16_t* o6h, uint16_t* o6l)
{
    int i = blockIdx.x * blockDim.x + threadIdx.x;
    if (i < 524288) {                       // x dense cols -> a0 [B,32]
        int b = i >> 5, k = i & 31;
        float v = (k < NDENSE) ? x[(size_t)b * XCOLS + k] : 0.f;
        split_h(v, a0h[i], a0l[i]);
    }
    else if (i < 540672)  seg_conv(i0, o0h, o0l, i - 524288,  13,   32,   512);
    else if (i < 671744)  seg_conv(i1, o1h, o1l, i - 540672,  512,  512,  256);
    else if (i < 704512)  seg_conv(i2, o2h, o2l, i - 671744,  256,  256,  128);
    else if (i < 1228800) seg_conv(i3, o3h, o3l, i - 704512,  506,  512,  1024);
    else if (i < 2277376) seg_conv(i4, o4h, o4l, i - 1228800, 1024, 1024, 1024);
    else if (i < 2801664) seg_conv(i5, o5h, o5l, i - 2277376, 1024, 1024, 512);
    else if (i < CONV_TOTAL) seg_conv(i6, o6h, o6l, i - 2801664, 512, 512, 256);
}

// ---------------------------------------------------------------------------
// GEMM (R12, unchanged): C[128x128 tile] = act(A @ B^T + bias).
// ---------------------------------------------------------------------------
#define PADH   40
#define PLANEB 10240
#define BUFB   40960
#define SMEM_BYTES (2 * BUFB)

__global__ __launch_bounds__(256, 2)
void gemm_hl(const uint16_t* __restrict__ Ah, const uint16_t* __restrict__ Al, int lda,
             const uint16_t* __restrict__ Bh, const uint16_t* __restrict__ Bl, int ldb,
             const float* __restrict__ bias,
             uint16_t* __restrict__ Ch, uint16_t* __restrict__ Cl,
             float* __restrict__ Cf, int ldc, int K, int relu)
{
    extern __shared__ __align__(16) uint16_t sm[];
    const uint32_t smem_base = (uint32_t)__cvta_generic_to_shared(sm);

    const int tid  = threadIdx.x;
    const int brow = blockIdx.y << 7;
    const int bcol = blockIdx.x << 7;
    const int warp = tid >> 5;
    const int lane = tid & 31;
    const int g    = lane >> 2;
    const int tg   = lane & 3;
    const int wm   = (warp & 3) << 5;
    const int wn   = (warp >> 2) << 6;

    const int r0c = (tid + 0)   >> 2, v0 = (tid + 0)   & 3;
    const int r1c = (tid + 256) >> 2, v1 = (tid + 256) & 3;

    const int lr  = lane & 7;
    const int sel = lane >> 3;
    const int a_row = ((sel & 1) << 3) + lr;
    const int a_kc  = sel >> 1;
    const uint32_t a_base = smem_base + (uint32_t)((wm + a_row) * 80 + a_kc * 16);
    const int b_row = ((sel >> 1) << 3) + lr;
    const int b_kc  = sel & 1;
    const uint32_t b_base = smem_base + 2 * PLANEB +
                            (uint32_t)((wn + b_row) * 80 + b_kc * 16);

    float acc[2][8][4];
#pragma unroll
    for (int mi = 0; mi < 2; mi++)
#pragma unroll
        for (int nj = 0; nj < 8; nj++)
#pragma unroll
            for (int q = 0; q < 4; q++) acc[mi][nj][q] = 0.f;

    const int nst = K >> 5;

    auto issue = [&](int s) {
        const int k0 = s << 5;
        const uint32_t base = smem_base + (uint32_t)(s & 1) * BUFB;
        {
            uint32_t d = base + (uint32_t)(r0c * 80 + v0 * 16);
            size_t ao = (size_t)(brow + r0c) * lda + k0 + v0 * 8;
            size_t bo = (size_t)(bcol + r0c) * ldb + k0 + v0 * 8;
            cpa16(d,              Ah + ao);
            cpa16(d + PLANEB,     Al + ao);
            cpa16(d + 2 * PLANEB, Bh + bo);
            cpa16(d + 3 * PLANEB, Bl + bo);
        }
        {
            uint32_t d = base + (uint32_t)(r1c * 80 + v1 * 16);
            size_t ao = (size_t)(brow + r1c) * lda + k0 + v1 * 8;
            size_t bo = (size_t)(bcol + r1c) * ldb + k0 + v1 * 8;
            cpa16(d,              Ah + ao);
            cpa16(d + PLANEB,     Al + ao);
            cpa16(d + 2 * PLANEB, Bh + bo);
            cpa16(d + 3 * PLANEB, Bl + bo);
        }
        asm volatile("cp.async.commit_group;" ::: "memory");
    };

    issue(0);

    for (int s = 0; s < nst; s++) {
        if (s + 1 < nst) {
            issue(s + 1);
            asm volatile("cp.async.wait_group 1;" ::: "memory");
        } else {
            asm volatile("cp.async.wait_group 0;" ::: "memory");
        }
        __syncthreads();

        const uint32_t buf = (uint32_t)(s & 1) * BUFB;

#pragma unroll
        for (int ks = 0; ks < 2; ks++) {
            const uint32_t ko = buf + (uint32_t)(ks * 32);
            uint32_t ah[2][4], al[2][4];
            ldsm4(ah[0], a_base + ko);
            ldsm4(ah[1], a_base + ko + 1280);
            ldsm4(al[0], a_base + ko + PLANEB);
            ldsm4(al[1], a_base + ko + PLANEB + 1280);
#pragma unroll
            for (int njp = 0; njp < 4; njp++) {
                uint32_t bh[4], bl[4];
                ldsm4(bh, b_base + ko + (uint32_t)(njp * 1280));
                ldsm4(bl, b_base + ko + (uint32_t)(njp * 1280) + PLANEB);
#pragma unroll
                for (int s2 = 0; s2 < 2; s2++) {
                    int nj = (njp << 1) + s2;
#pragma unroll
                    for (int mi = 0; mi < 2; mi++) {
                        mma16(acc[mi][nj], ah[mi], bh[2*s2], bh[2*s2+1]);
                        mma16(acc[mi][nj], al[mi], bh[2*s2], bh[2*s2+1]);
                        mma16(acc[mi][nj], ah[mi], bl[2*s2], bl[2*s2+1]);
                    }
                }
            }
        }
        __syncthreads();
    }

#pragma unroll
    for (int nj = 0; nj < 8; nj++) {
        int col = bcol + wn + (nj << 3) + (tg << 1);
        float b0 = __ldg(&bias[col]), b1 = __ldg(&bias[col + 1]);
#pragma unroll
        for (int mi = 0; mi < 2; mi++) {
            int r0 = brow + wm + (mi << 4) + g;
            float v0 = acc[mi][nj][0] + b0;
            float v1 = acc[mi][nj][1] + b1;
            float v2 = acc[mi][nj][2] + b0;
            float v3 = acc[mi][nj][3] + b1;
            if (relu) {
                v0 = fmaxf(v0, 0.f); v1 = fmaxf(v1, 0.f);
                v2 = fmaxf(v2, 0.f); v3 = fmaxf(v3, 0.f);
            }
            if (Cf) {
                *(float2*)(Cf + (size_t)r0 * ldc + col)       = make_float2(v0, v1);
                *(float2*)(Cf + (size_t)(r0 + 8) * ldc + col) = make_float2(v2, v3);
            } else {
                uint16_t h0, l0, h1x, l1x, h2, l2, h3, l3;
                split_h(v0, h0, l0); split_h(v1, h1x, l1x);
                split_h(v2, h2, l2); split_h(v3, h3, l3);
                *(uint32_t*)(Ch + (size_t)r0 * ldc + col) =
                    (uint32_t)h0 | ((uint32_t)h1x << 16);
                *(uint32_t*)(Cl + (size_t)r0 * ldc + col) =
                    (uint32_t)l0 | ((uint32_t)l1x << 16);
                *(uint32_t*)(Ch + (size_t)(r0 + 8) * ldc + col) =
                    (uint32_t)h2 | ((uint32_t)h3 << 16);
                *(uint32_t*)(Cl + (size_t)(r0 + 8) * ldc + col) =
                    (uint32_t)l2 | ((uint32_t)l3 << 16);
            }
        }
    }
}

// ---------------------------------------------------------------------------
// Fused embedding gather + dot interaction, K-halved (two 64-col passes).
// One warp per sample; 28 lanes each own a 4x4 triu tile of the 27x27 Gram;
// acc registers persist across the two passes. smem/warp halves vs R12 ->
// occupancy-cap ~37% (launch_bounds 64,12).
// ---------------------------------------------------------------------------
#define FH 68   // floats per smem row (64 + 4 pad)

__global__ __launch_bounds__(64, 12)
void interact_kernel(const float* __restrict__ x,
                     const float* __restrict__ emb,
                     const float* __restrict__ bot,
                     uint16_t* __restrict__ t0h, uint16_t* __restrict__ t0l)
{
    __shared__ float feat[2][NFEAT][FH];
    const int warp = threadIdx.x >> 5;
    const int lane = threadIdx.x & 31;
    const int b    = (blockIdx.x << 1) + warp;
    float (*f)[FH] = feat[warp];

    // categorical ids (once)
    int myidx = 0;
    if (lane < NSPARSE) {
        float c = x[(size_t)b * XCOLS + NDENSE + lane];
        myidx = ((int)c) % VOCAB;
    }

    // full bottom row for the t0 bottom-part write
    float4 botv = *(const float4*)(bot + (size_t)b * EMBDIM + lane * 4);
    {
        uint16_t hb[4], lb[4];
        split_h(botv.x, hb[0], lb[0]);
        split_h(botv.y, hb[1], lb[1]);
        split_h(botv.z, hb[2], lb[2]);
        split_h(botv.w, hb[3], lb[3]);
        *(uint2*)(t0h + (size_t)b * 512 + lane * 4) = *(uint2*)hb;
        *(uint2*)(t0l + (size_t)b * 512 + lane * 4) = *(uint2*)lb;
    }
    if (lane < 6) {
        t0h[(size_t)b * 512 + 506 + lane] = 0;
        t0l[(size_t)b * 512 + 506 + lane] = 0;
    }

    // tile mapping (same as R12): lanes 0..27 -> triu 4x4 tiles of 7x7 grid
    int t = (lane < 28) ? lane : 0;
    int gi = 0;
    while (t >= 7 - gi) { t -= 7 - gi; gi++; }
    int gj = gi + t;
    int i0 = gi << 2, j0 = gj << 2;

    // conflict-avoiding chunk stagger: lanes 16 apart get different chunks
    const int stag = lane + ((lane >> 4) << 3);

    float acc[4][4];
#pragma unroll
    for (int i = 0; i < 4; i++)
#pragma unroll
        for (int j = 0; j < 4; j++) acc[i][j] = 0.f;

#pragma unroll
    for (int half = 0; half < 2; half++) {
        const int co = half << 6;   // column offset 0 or 64

        // stage 27 rows x 64 cols: each lane loads float2 of each row
        *(float2*)&f[0][lane * 2] =
            *(const float2*)(bot + (size_t)b * EMBDIM + co + lane * 2);
#pragma unroll 2
        for (int j = 0; j < NSPARSE; j++) {
            int row = __shfl_sync(0xffffffffu, myidx, j);
            *(float2*)&f[1 + j][lane * 2] =
                *(const float2*)(emb + (size_t)row * EMBDIM + co + lane * 2);
        }
        __syncwarp();

        if (lane < 28) {
#pragma unroll 4
            for (int c = 0; c < 16; c++) {
                int d = ((c + stag) & 15) << 2;
                float4 ai[4], bj[4];
#pragma unroll
                for (int ii = 0; ii < 4; ii++)
                    ai[ii] = (i0 + ii < NFEAT) ? *(const float4*)&f[i0 + ii][d]
                                               : make_float4(0.f, 0.f, 0.f, 0.f);
#pragma unroll
                for (int jj = 0; jj < 4; jj++)
                    bj[jj] = (j0 + jj < NFEAT) ? *(const float4*)&f[j0 + jj][d]
                                               : make_float4(0.f, 0.f, 0.f, 0.f);
#pragma unroll
                for (int ii = 0; ii < 4; ii++)
#pragma unroll
                    for (int jj = 0; jj < 4; jj++) {
                        acc[ii][jj] = fmaf(ai[ii].x, bj[jj].x, acc[ii][jj]);
                        acc[ii][jj] = fmaf(ai[ii].y, bj[jj].y, acc[ii][jj]);
                        acc[ii][jj] = fmaf(ai[ii].z, bj[jj].z, acc[ii][jj]);
                        acc[ii][jj] = fmaf(ai[ii].w, bj[jj].w, acc[ii][jj]);
                    }
            }
        }
        __syncwarp();
    }

    if (lane < 28) {
        uint16_t* oh = t0h + (size_t)b * 512 + EMBDIM;
        uint16_t* ol = t0l + (size_t)b * 512 + EMBDIM;
#pragma unroll
        for (int ii = 0; ii < 4; ii++)
#pragma unroll
            for (int jj = 0; jj < 4; jj++) {
                int i = i0 + ii, j = j0 + jj;
                if (i < NFEAT && j < NFEAT && i <= j) {
                    int off = i * NFEAT - ((i * (i - 1)) >> 1) + (j - i);
                    uint16_t h, l;
                    split_h(acc[ii][jj], h, l);
                    oh[off] = h; ol[off] = l;
                }
            }
    }
}

// ---------------------------------------------------------------------------
// Final layer: out[b] = (t4h+t4l)[b,:] @ w[256,1] + bias. One warp per row.
// ---------------------------------------------------------------------------
__global__ __launch_bounds__(256)
void final_layer(const uint16_t* __restrict__ t4h, const uint16_t* __restrict__ t4l,
                 const float* __restrict__ w,
                 const float* __restrict__ bias,
                 float* __restrict__ out)
{
    const int warp = threadIdx.x >> 5;
    const int lane = threadIdx.x & 31;
    const int row  = (blockIdx.x << 3) + warp;

    float s = 0.f;
#pragma unroll
    for (int k = lane; k < 256; k += 32) {
        float v = __half2float(__ushort_as_half(t4h[(size_t)row * 256 + k])) +
                  __half2float(__ushort_as_half(t4l[(size_t)row * 256 + k]));
        s = fmaf(v, __ldg(&w[k]), s);
    }
#pragma unroll
    for (int o = 16; o; o >>= 1)
        s += __shfl_down_sync(0xffffffffu, s, o);
    if (lane == 0) out[row] = s + bias[0];
}

// ---------------------------------------------------------------------------
extern "C" void kernel_launch(void* const* d_in, const int* in_sizes, int n_in,
                              void* d_out, int out_size)
{
    (void)in_sizes; (void)n_in; (void)out_size;

    const float* x   = (const float*)d_in[0];
    const float* bw0 = (const float*)d_in[2];
    const float* bb0 = (const float*)d_in[3];
    const float* bw1 = (const float*)d_in[4];
    const float* bb1 = (const float*)d_in[5];
    const float* bw2 = (const float*)d_in[6];
    const float* bb2 = (const float*)d_in[7];
    const float* emb = (const float*)d_in[8];
    const float* tw0 = (const float*)d_in[9];
    const float* tb0 = (const float*)d_in[10];
    const float* tw1 = (const float*)d_in[11];
    const float* tb1 = (const float*)d_in[12];
    const float* tw2 = (const float*)d_in[13];
    const float* tb2 = (const float*)d_in[14];
    const float* tw3 = (const float*)d_in[15];
    const float* tb3 = (const float*)d_in[16];
    const float* tw4 = (const float*)d_in[17];
    const float* tb4 = (const float*)d_in[18];
    float* out = (float*)d_out;

    cudaFuncSetAttribute(gemm_hl, cudaFuncAttributeMaxDynamicSharedMemorySize,
                         SMEM_BYTES);

    uint16_t *a0h,*a0l,*h1h,*h1l,*h2h,*h2l,*t0h,*t0l,*t1h,*t1l,*t2h,*t2l,*t3h,*t3l,*t4h,*t4l;
    uint16_t *w0h,*w0l,*w1h,*w1l,*w2h,*w2l,*x0h,*x0l,*x1h,*x1l,*x2h,*x2l,*x3h,*x3l;
    float *bot;
    cudaGetSymbolAddress((void**)&a0h, g_a0h); cudaGetSymbolAddress((void**)&a0l, g_a0l);
    cudaGetSymbolAddress((void**)&h1h, g_h1h); cudaGetSymbolAddress((void**)&h1l, g_h1l);
    cudaGetSymbolAddress((void**)&h2h, g_h2h); cudaGetSymbolAddress((void**)&h2l, g_h2l);
    cudaGetSymbolAddress((void**)&bot, g_bot);
    cudaGetSymbolAddress((void**)&t0h, g_t0h); cudaGetSymbolAddress((void**)&t0l, g_t0l);
    cudaGetSymbolAddress((void**)&t1h, g_t1h); cudaGetSymbolAddress((void**)&t1l, g_t1l);
    cudaGetSymbolAddress((void**)&t2h, g_t2h); cudaGetSymbolAddress((void**)&t2l, g_t2l);
    cudaGetSymbolAddress((void**)&t3h, g_t3h); cudaGetSymbolAddress((void**)&t3l, g_t3l);
    cudaGetSymbolAddress((void**)&t4h, g_t4h); cudaGetSymbolAddress((void**)&t4l, g_t4l);
    cudaGetSymbolAddress((void**)&w0h, g_w0h); cudaGetSymbolAddress((void**)&w0l, g_w0l);
    cudaGetSymbolAddress((void**)&w1h, g_w1h); cudaGetSymbolAddress((void**)&w1l, g_w1l);
    cudaGetSymbolAddress((void**)&w2h, g_w2h); cudaGetSymbolAddress((void**)&w2l, g_w2l);
    cudaGetSymbolAddress((void**)&x0h, g_tw0h); cudaGetSymbolAddress((void**)&x0l, g_tw0l);
    cudaGetSymbolAddress((void**)&x1h, g_tw1h); cudaGetSymbolAddress((void**)&x1l, g_tw1l);
    cudaGetSymbolAddress((void**)&x2h, g_tw2h); cudaGetSymbolAddress((void**)&x2l, g_tw2l);
    cudaGetSymbolAddress((void**)&x3h, g_tw3h); cudaGetSymbolAddress((void**)&x3l, g_tw3l);

    // ---- fused prepass ----
    conv_all<<<(CONV_TOTAL + 255) / 256, 256>>>(
        x, bw0, bw1, bw2, tw0, tw1, tw2, tw3,
        a0h, a0l,
        w0h, w0l, w1h, w1l, w2h, w2l,
        x0h, x0l, x1h, x1l, x2h, x2l, x3h, x3l);

    const int MB = BATCH / 128;

    // bottom MLP: 13->512->256->128 (relu)
    gemm_hl<<<dim3(4, MB), 256, SMEM_BYTES>>>(a0h, a0l, 32,  w0h, w0l, 32,
                                              bb0, h1h, h1l, nullptr, 512, 32, 1);
    gemm_hl<<<dim3(2, MB), 256, SMEM_BYTES>>>(h1h, h1l, 512, w1h, w1l, 512,
                                              bb1, h2h, h2l, nullptr, 256, 512, 1);
    gemm_hl<<<dim3(1, MB), 256, SMEM_BYTES>>>(h2h, h2l, 256, w2h, w2l, 256,
                                              bb2, nullptr, nullptr, bot, 128, 256, 1);

    // gather + interaction -> t0 planes [B,512]
    interact_kernel<<<BATCH / 2, 64>>>(x, emb, bot, t0h, t0l);

    // top MLP: 506->1024->1024->512->256 (relu)
    gemm_hl<<<dim3(8, MB), 256, SMEM_BYTES>>>(t0h, t0l, 512,  x0h, x0l, 512,
                                              tb0, t1h, t1l, nullptr, 1024, 512,  1);
    gemm_hl<<<dim3(8, MB), 256, SMEM_BYTES>>>(t1h, t1l, 1024, x1h, x1l, 1024,
                                              tb1, t2h, t2l, nullptr, 1024, 1024, 1);
    gemm_hl<<<dim3(4, MB), 256, SMEM_BYTES>>>(t2h, t2l, 1024, x2h, x2l, 1024,
                                              tb2, t3h, t3l, nullptr, 512,  1024, 1);
    gemm_hl<<<dim3(2, MB), 256, SMEM_BYTES>>>(t3h, t3l, 512,  x3h, x3l, 512,
                                              tb3, t4h, t4l, nullptr, 256,  512,  1);

    // final: 256 -> 1 (no relu)
    final_layer<<<BATCH / 8, 256>>>(t4h, t4l, tw4, tb4, out);
}

// round 14
// speedup vs baseline: 1.0990x; 1.0990x over previous
#include <cuda_runtime.h>
#include <cuda_fp16.h>
#include <cstdint>

// ---------------------------------------------------------------------------
// DLRM forward. GEMMs via mma.sync.m16n8k16.f16, 3-term fp16 split
// (Ah*Bh + Al*Bh + Ah*Bl), fp32 accum (R12 GEMM — at the mma.sync wall).
// R14: interact Gram computed on tensor cores (32x32x128, 3-term split),
// gather stages rows directly as hi/lo f16 planes. GEMM/prepass = R12.
// ---------------------------------------------------------------------------

#define BATCH   16384
#define NDENSE  13
#define NSPARSE 26
#define XCOLS   39
#define EMBDIM  128
#define VOCAB   1000000
#define NFEAT   27

// -------------------- scratch planes (device globals) ----------------------
__device__ __align__(16) uint16_t g_a0h[BATCH * 32],   g_a0l[BATCH * 32];
__device__ __align__(16) uint16_t g_h1h[BATCH * 512],  g_h1l[BATCH * 512];
__device__ __align__(16) uint16_t g_h2h[BATCH * 256],  g_h2l[BATCH * 256];
__device__ __align__(16) float    g_bot[BATCH * 128];
__device__ __align__(16) uint16_t g_t0h[BATCH * 512],  g_t0l[BATCH * 512];
__device__ __align__(16) uint16_t g_t1h[BATCH * 1024], g_t1l[BATCH * 1024];
__device__ __align__(16) uint16_t g_t2h[BATCH * 1024], g_t2l[BATCH * 1024];
__device__ __align__(16) uint16_t g_t3h[BATCH * 512],  g_t3l[BATCH * 512];
__device__ __align__(16) uint16_t g_t4h[BATCH * 256],  g_t4l[BATCH * 256];
// transposed weight planes [N][Kpad]
__device__ __align__(16) uint16_t g_w0h [512  * 32],   g_w0l [512  * 32];
__device__ __align__(16) uint16_t g_w1h [256  * 512],  g_w1l [256  * 512];
__device__ __align__(16) uint16_t g_w2h [128  * 256],  g_w2l [128  * 256];
__device__ __align__(16) uint16_t g_tw0h[1024 * 512],  g_tw0l[1024 * 512];
__device__ __align__(16) uint16_t g_tw1h[1024 * 1024], g_tw1l[1024 * 1024];
__device__ __align__(16) uint16_t g_tw2h[512  * 1024], g_tw2l[512  * 1024];
__device__ __align__(16) uint16_t g_tw3h[256  * 512],  g_tw3l[256  * 512];

// ---------------------------------------------------------------------------
__device__ __forceinline__ void split_h(float v, uint16_t& h, uint16_t& l) {
    __half hh = __float2half_rn(v);
    __half ll = __float2half_rn(v - __half2float(hh));
    h = __half_as_ushort(hh);
    l = __half_as_ushort(ll);
}

__device__ __forceinline__ void mma16(float* c, const uint32_t* a,
                                      uint32_t b0, uint32_t b1) {
    asm volatile(
        "mma.sync.aligned.m16n8k16.row.col.f32.f16.f16.f32 "
        "{%0,%1,%2,%3}, {%4,%5,%6,%7}, {%8,%9}, {%0,%1,%2,%3};\n"
        : "+f"(c[0]), "+f"(c[1]), "+f"(c[2]), "+f"(c[3])
        : "r"(a[0]), "r"(a[1]), "r"(a[2]), "r"(a[3]), "r"(b0), "r"(b1));
}

__device__ __forceinline__ void ldsm4(uint32_t* r, uint32_t addr) {
    asm volatile(
        "ldmatrix.sync.aligned.m8n8.x4.shared.b16 {%0,%1,%2,%3}, [%4];\n"
        : "=r"(r[0]), "=r"(r[1]), "=r"(r[2]), "=r"(r[3]) : "r"(addr));
}

__device__ __forceinline__ void cpa16(uint32_t dst, const void* src) {
    asm volatile("cp.async.cg.shared.global [%0], [%1], 16;\n"
                 :: "r"(dst), "l"(src));
}

// ---------------------------------------------------------------------------
// Fused prepass: split/transpose ALL weights + input to f16 planes, 1 launch.
// ---------------------------------------------------------------------------
__device__ __forceinline__ void seg_conv(const float* __restrict__ in,
                                         uint16_t* __restrict__ oh,
                                         uint16_t* __restrict__ ol,
                                         int j, int K, int Kpad, int N) {
    int n = j / Kpad, k = j - n * Kpad;
    float v = (k < K) ? in[(size_t)k * N + n] : 0.f;
    split_h(v, oh[j], ol[j]);
}

#define CONV_TOTAL 2932736

__global__ void conv_all(const float* __restrict__ x,
    const float* __restrict__ i0, const float* __restrict__ i1,
    const float* __restrict__ i2, const float* __restrict__ i3,
    const float* __restrict__ i4, const float* __restrict__ i5,
    const float* __restrict__ i6,
    uint16_t* a0h, uint16_t* a0l,
    uint16_t* o0h, uint16_t* o0l, uint16_t* o1h, uint16_t* o1l,
    uint16_t* o2h, uint16_t* o2l, uint16_t* o3h, uint16_t* o3l,
    uint16_t* o4h, uint16_t* o4l, uint16_t* o5h, uint16_t* o5l,
    uint16_t* o6h, uint16_t* o6l)
{
    int i = blockIdx.x * blockDim.x + threadIdx.x;
    if (i < 524288) {                       // x dense cols -> a0 [B,32]
        int b = i >> 5, k = i & 31;
        float v = (k < NDENSE) ? x[(size_t)b * XCOLS + k] : 0.f;
        split_h(v, a0h[i], a0l[i]);
    }
    else if (i < 540672)  seg_conv(i0, o0h, o0l, i - 524288,  13,   32,   512);
    else if (i < 671744)  seg_conv(i1, o1h, o1l, i - 540672,  512,  512,  256);
    else if (i < 704512)  seg_conv(i2, o2h, o2l, i - 671744,  256,  256,  128);
    else if (i < 1228800) seg_conv(i3, o3h, o3l, i - 704512,  506,  512,  1024);
    else if (i < 2277376) seg_conv(i4, o4h, o4l, i - 1228800, 1024, 1024, 1024);
    else if (i < 2801664) seg_conv(i5, o5h, o5l, i - 2277376, 1024, 1024, 512);
    else if (i < CONV_TOTAL) seg_conv(i6, o6h, o6l, i - 2801664, 512, 512, 256);
}

// ---------------------------------------------------------------------------
// GEMM (R12, unchanged): C[128x128 tile] = act(A @ B^T + bias).
// ---------------------------------------------------------------------------
#define PADH   40
#define PLANEB 10240
#define BUFB   40960
#define SMEM_BYTES (2 * BUFB)

__global__ __launch_bounds__(256, 2)
void gemm_hl(const uint16_t* __restrict__ Ah, const uint16_t* __restrict__ Al, int lda,
             const uint16_t* __restrict__ Bh, const uint16_t* __restrict__ Bl, int ldb,
             const float* __restrict__ bias,
             uint16_t* __restrict__ Ch, uint16_t* __restrict__ Cl,
             float* __restrict__ Cf, int ldc, int K, int relu)
{
    extern __shared__ __align__(16) uint16_t sm[];
    const uint32_t smem_base = (uint32_t)__cvta_generic_to_shared(sm);

    const int tid  = threadIdx.x;
    const int brow = blockIdx.y << 7;
    const int bcol = blockIdx.x << 7;
    const int warp = tid >> 5;
    const int lane = tid & 31;
    const int g    = lane >> 2;
    const int tg   = lane & 3;
    const int wm   = (warp & 3) << 5;
    const int wn   = (warp >> 2) << 6;

    const int r0c = (tid + 0)   >> 2, v0 = (tid + 0)   & 3;
    const int r1c = (tid + 256) >> 2, v1 = (tid + 256) & 3;

    const int lr  = lane & 7;
    const int sel = lane >> 3;
    const int a_row = ((sel & 1) << 3) + lr;
    const int a_kc  = sel >> 1;
    const uint32_t a_base = smem_base + (uint32_t)((wm + a_row) * 80 + a_kc * 16);
    const int b_row = ((sel >> 1) << 3) + lr;
    const int b_kc  = sel & 1;
    const uint32_t b_base = smem_base + 2 * PLANEB +
                            (uint32_t)((wn + b_row) * 80 + b_kc * 16);

    float acc[2][8][4];
#pragma unroll
    for (int mi = 0; mi < 2; mi++)
#pragma unroll
        for (int nj = 0; nj < 8; nj++)
#pragma unroll
            for (int q = 0; q < 4; q++) acc[mi][nj][q] = 0.f;

    const int nst = K >> 5;

    auto issue = [&](int s) {
        const int k0 = s << 5;
        const uint32_t base = smem_base + (uint32_t)(s & 1) * BUFB;
        {
            uint32_t d = base + (uint32_t)(r0c * 80 + v0 * 16);
            size_t ao = (size_t)(brow + r0c) * lda + k0 + v0 * 8;
            size_t bo = (size_t)(bcol + r0c) * ldb + k0 + v0 * 8;
            cpa16(d,              Ah + ao);
            cpa16(d + PLANEB,     Al + ao);
            cpa16(d + 2 * PLANEB, Bh + bo);
            cpa16(d + 3 * PLANEB, Bl + bo);
        }
        {
            uint32_t d = base + (uint32_t)(r1c * 80 + v1 * 16);
            size_t ao = (size_t)(brow + r1c) * lda + k0 + v1 * 8;
            size_t bo = (size_t)(bcol + r1c) * ldb + k0 + v1 * 8;
            cpa16(d,              Ah + ao);
            cpa16(d + PLANEB,     Al + ao);
            cpa16(d + 2 * PLANEB, Bh + bo);
            cpa16(d + 3 * PLANEB, Bl + bo);
        }
        asm volatile("cp.async.commit_group;" ::: "memory");
    };

    issue(0);

    for (int s = 0; s < nst; s++) {
        if (s + 1 < nst) {
            issue(s + 1);
            asm volatile("cp.async.wait_group 1;" ::: "memory");
        } else {
            asm volatile("cp.async.wait_group 0;" ::: "memory");
        }
        __syncthreads();

        const uint32_t buf = (uint32_t)(s & 1) * BUFB;

#pragma unroll
        for (int ks = 0; ks < 2; ks++) {
            const uint32_t ko = buf + (uint32_t)(ks * 32);
            uint32_t ah[2][4], al[2][4];
            ldsm4(ah[0], a_base + ko);
            ldsm4(ah[1], a_base + ko + 1280);
            ldsm4(al[0], a_base + ko + PLANEB);
            ldsm4(al[1], a_base + ko + PLANEB + 1280);
#pragma unroll
            for (int njp = 0; njp < 4; njp++) {
                uint32_t bh[4], bl[4];
                ldsm4(bh, b_base + ko + (uint32_t)(njp * 1280));
                ldsm4(bl, b_base + ko + (uint32_t)(njp * 1280) + PLANEB);
#pragma unroll
                for (int s2 = 0; s2 < 2; s2++) {
                    int nj = (njp << 1) + s2;
#pragma unroll
                    for (int mi = 0; mi < 2; mi++) {
                        mma16(acc[mi][nj], ah[mi], bh[2*s2], bh[2*s2+1]);
                        mma16(acc[mi][nj], al[mi], bh[2*s2], bh[2*s2+1]);
                        mma16(acc[mi][nj], ah[mi], bl[2*s2], bl[2*s2+1]);
                    }
                }
            }
        }
        __syncthreads();
    }

#pragma unroll
    for (int nj = 0; nj < 8; nj++) {
        int col = bcol + wn + (nj << 3) + (tg << 1);
        float b0 = __ldg(&bias[col]), b1 = __ldg(&bias[col + 1]);
#pragma unroll
        for (int mi = 0; mi < 2; mi++) {
            int r0 = brow + wm + (mi << 4) + g;
            float v0 = acc[mi][nj][0] + b0;
            float v1 = acc[mi][nj][1] + b1;
            float v2 = acc[mi][nj][2] + b0;
            float v3 = acc[mi][nj][3] + b1;
            if (relu) {
                v0 = fmaxf(v0, 0.f); v1 = fmaxf(v1, 0.f);
                v2 = fmaxf(v2, 0.f); v3 = fmaxf(v3, 0.f);
            }
            if (Cf) {
                *(float2*)(Cf + (size_t)r0 * ldc + col)       = make_float2(v0, v1);
                *(float2*)(Cf + (size_t)(r0 + 8) * ldc + col) = make_float2(v2, v3);
            } else {
                uint16_t h0, l0, h1x, l1x, h2, l2, h3, l3;
                split_h(v0, h0, l0); split_h(v1, h1x, l1x);
                split_h(v2, h2, l2); split_h(v3, h3, l3);
                *(uint32_t*)(Ch + (size_t)r0 * ldc + col) =
                    (uint32_t)h0 | ((uint32_t)h1x << 16);
                *(uint32_t*)(Cl + (size_t)r0 * ldc + col) =
                    (uint32_t)l0 | ((uint32_t)l1x << 16);
                *(uint32_t*)(Ch + (size_t)(r0 + 8) * ldc + col) =
                    (uint32_t)h2 | ((uint32_t)h3 << 16);
                *(uint32_t*)(Cl + (size_t)(r0 + 8) * ldc + col) =
                    (uint32_t)l2 | ((uint32_t)l3 << 16);
            }
        }
    }
}

// ---------------------------------------------------------------------------
// Fused embedding gather + dot interaction on TENSOR CORES.
// One warp per sample. feat padded to 32x128, stored as hi/lo f16 planes
// (row stride 272B -> 17x16B, coprime 8 -> ldmatrix conflict-free).
// Gram = F F^T via m16n8k16 (2 m-tiles x 4 n-tiles x 8 k-chunks x 3 terms).
// Same lane mappings as gemm_hl (proven). Epilogue scatters triu.
// ---------------------------------------------------------------------------
#define SROW   136                 // halves per feat row (272 B)
#define SROWB  272
#define SPLANE (32 * SROW)         // halves per plane
#define SPLB   (SPLANE * 2)        // bytes per plane (8704)

__global__ __launch_bounds__(64)
void interact_kernel(const float* __restrict__ x,
                     const float* __restrict__ emb,
                     const float* __restrict__ bot,
                     uint16_t* __restrict__ t0h, uint16_t* __restrict__ t0l)
{
    __shared__ __align__(16) uint16_t fs[2][2 * SPLANE];
    const int warp = threadIdx.x >> 5;
    const int lane = threadIdx.x & 31;
    const int b    = (blockIdx.x << 1) + warp;
    uint16_t* fh = fs[warp];
    uint16_t* fl = fh + SPLANE;
    const uint32_t sbase = (uint32_t)__cvta_generic_to_shared(fh);

    // categorical ids
    int myidx = 0;
    if (lane < NSPARSE) {
        float c = x[(size_t)b * XCOLS + NDENSE + lane];
        myidx = ((int)c) % VOCAB;
    }

    // row 0 = bottom-MLP output; also write t0 bottom part + pad
    {
        float4 v = *(const float4*)(bot + (size_t)b * EMBDIM + lane * 4);
        uint16_t hb[4], lb[4];
        split_h(v.x, hb[0], lb[0]); split_h(v.y, hb[1], lb[1]);
        split_h(v.z, hb[2], lb[2]); split_h(v.w, hb[3], lb[3]);
        *(uint2*)&fh[lane * 4] = *(uint2*)hb;
        *(uint2*)&fl[lane * 4] = *(uint2*)lb;
        *(uint2*)(t0h + (size_t)b * 512 + lane * 4) = *(uint2*)hb;
        *(uint2*)(t0l + (size_t)b * 512 + lane * 4) = *(uint2*)lb;
    }
    if (lane < 6) {
        t0h[(size_t)b * 512 + 506 + lane] = 0;
        t0l[(size_t)b * 512 + 506 + lane] = 0;
    }

    // zero pad rows 27..31
#pragma unroll
    for (int r = 27; r < 32; r++) {
        *(uint2*)&fh[r * SROW + lane * 4] = make_uint2(0u, 0u);
        *(uint2*)&fl[r * SROW + lane * 4] = make_uint2(0u, 0u);
    }

    // gather rows 1..26 (coalesced 512B rows), split at staging
    for (int j = 0; j < NSPARSE; j++) {
        int row = __shfl_sync(0xffffffffu, myidx, j);
        float4 v = *(const float4*)(emb + (size_t)row * EMBDIM + lane * 4);
        uint16_t hb[4], lb[4];
        split_h(v.x, hb[0], lb[0]); split_h(v.y, hb[1], lb[1]);
        split_h(v.z, hb[2], lb[2]); split_h(v.w, hb[3], lb[3]);
        *(uint2*)&fh[(1 + j) * SROW + lane * 4] = *(uint2*)hb;
        *(uint2*)&fl[(1 + j) * SROW + lane * 4] = *(uint2*)lb;
    }
    __syncwarp();

    // ldmatrix lane addressing (identical pattern to gemm_hl)
    const int lr  = lane & 7;
    const int sel = lane >> 3;
    const int a_row = ((sel & 1) << 3) + lr;
    const int a_kc  = sel >> 1;
    const uint32_t a_base = sbase + (uint32_t)(a_row * SROWB + a_kc * 16);
    const int b_row = ((sel >> 1) << 3) + lr;
    const int b_kc  = sel & 1;
    const uint32_t b_base = sbase + (uint32_t)(b_row * SROWB + b_kc * 16);

    float acc[2][4][4];
#pragma unroll
    for (int mi = 0; mi < 2; mi++)
#pragma unroll
        for (int nj = 0; nj < 4; nj++)
#pragma unroll
            for (int q = 0; q < 4; q++) acc[mi][nj][q] = 0.f;

#pragma unroll
    for (int k = 0; k < 8; k++) {
        const uint32_t ko = (uint32_t)(k * 32);
        uint32_t ah[2][4], al[2][4];
        ldsm4(ah[0], a_base + ko);
        ldsm4(ah[1], a_base + ko + 16 * SROWB);
        ldsm4(al[0], a_base + ko + SPLB);
        ldsm4(al[1], a_base + ko + SPLB + 16 * SROWB);
#pragma unroll
        for (int njp = 0; njp < 2; njp++) {
            const uint32_t no = (uint32_t)(njp * 16 * SROWB);
            uint32_t bh[4], bl[4];
            ldsm4(bh, b_base + ko + no);
            ldsm4(bl, b_base + ko + no + SPLB);
#pragma unroll
            for (int s2 = 0; s2 < 2; s2++) {
                int nj = (njp << 1) + s2;
#pragma unroll
                for (int mi = 0; mi < 2; mi++) {
                    mma16(acc[mi][nj], ah[mi], bh[2*s2], bh[2*s2+1]);
                    mma16(acc[mi][nj], al[mi], bh[2*s2], bh[2*s2+1]);
                    mma16(acc[mi][nj], ah[mi], bl[2*s2], bl[2*s2+1]);
                }
            }
        }
    }

    // epilogue: scatter c-frags into triu(27) ordering
    const int g  = lane >> 2;
    const int tg = lane & 3;
    uint16_t* oh = t0h + (size_t)b * 512 + EMBDIM;
    uint16_t* ol = t0l + (size_t)b * 512 + EMBDIM;
#pragma unroll
    for (int mi = 0; mi < 2; mi++)
#pragma unroll
        for (int nj = 0; nj < 4; nj++)
#pragma unroll
            for (int q = 0; q < 4; q++) {
                int i = (mi << 4) + g + ((q & 2) << 2);
                int j = (nj << 3) + (tg << 1) + (q & 1);
                if (i <= j && j < NFEAT) {
                    int off = i * NFEAT - ((i * (i - 1)) >> 1) + (j - i);
                    uint16_t h, l;
                    split_h(acc[mi][nj][q], h, l);
                    oh[off] = h; ol[off] = l;
                }
            }
}

// ---------------------------------------------------------------------------
// Final layer: out[b] = (t4h+t4l)[b,:] @ w[256,1] + bias. One warp per row.
// ---------------------------------------------------------------------------
__global__ __launch_bounds__(256)
void final_layer(const uint16_t* __restrict__ t4h, const uint16_t* __restrict__ t4l,
                 const float* __restrict__ w,
                 const float* __restrict__ bias,
                 float* __restrict__ out)
{
    const int warp = threadIdx.x >> 5;
    const int lane = threadIdx.x & 31;
    const int row  = (blockIdx.x << 3) + warp;

    float s = 0.f;
#pragma unroll
    for (int k = lane; k < 256; k += 32) {
        float v = __half2float(__ushort_as_half(t4h[(size_t)row * 256 + k])) +
                  __half2float(__ushort_as_half(t4l[(size_t)row * 256 + k]));
        s = fmaf(v, __ldg(&w[k]), s);
    }
#pragma unroll
    for (int o = 16; o; o >>= 1)
        s += __shfl_down_sync(0xffffffffu, s, o);
    if (lane == 0) out[row] = s + bias[0];
}

// ---------------------------------------------------------------------------
extern "C" void kernel_launch(void* const* d_in, const int* in_sizes, int n_in,
                              void* d_out, int out_size)
{
    (void)in_sizes; (void)n_in; (void)out_size;

    const float* x   = (const float*)d_in[0];
    const float* bw0 = (const float*)d_in[2];
    const float* bb0 = (const float*)d_in[3];
    const float* bw1 = (const float*)d_in[4];
    const float* bb1 = (const float*)d_in[5];
    const float* bw2 = (const float*)d_in[6];
    const float* bb2 = (const float*)d_in[7];
    const float* emb = (const float*)d_in[8];
    const float* tw0 = (const float*)d_in[9];
    const float* tb0 = (const float*)d_in[10];
    const float* tw1 = (const float*)d_in[11];
    const float* tb1 = (const float*)d_in[12];
    const float* tw2 = (const float*)d_in[13];
    const float* tb2 = (const float*)d_in[14];
    const float* tw3 = (const float*)d_in[15];
    const float* tb3 = (const float*)d_in[16];
    const float* tw4 = (const float*)d_in[17];
    const float* tb4 = (const float*)d_in[18];
    float* out = (float*)d_out;

    cudaFuncSetAttribute(gemm_hl, cudaFuncAttributeMaxDynamicSharedMemorySize,
                         SMEM_BYTES);

    uint16_t *a0h,*a0l,*h1h,*h1l,*h2h,*h2l,*t0h,*t0l,*t1h,*t1l,*t2h,*t2l,*t3h,*t3l,*t4h,*t4l;
    uint16_t *w0h,*w0l,*w1h,*w1l,*w2h,*w2l,*x0h,*x0l,*x1h,*x1l,*x2h,*x2l,*x3h,*x3l;
    float *bot;
    cudaGetSymbolAddress((void**)&a0h, g_a0h); cudaGetSymbolAddress((void**)&a0l, g_a0l);
    cudaGetSymbolAddress((void**)&h1h, g_h1h); cudaGetSymbolAddress((void**)&h1l, g_h1l);
    cudaGetSymbolAddress((void**)&h2h, g_h2h); cudaGetSymbolAddress((void**)&h2l, g_h2l);
    cudaGetSymbolAddress((void**)&bot, g_bot);
    cudaGetSymbolAddress((void**)&t0h, g_t0h); cudaGetSymbolAddress((void**)&t0l, g_t0l);
    cudaGetSymbolAddress((void**)&t1h, g_t1h); cudaGetSymbolAddress((void**)&t1l, g_t1l);
    cudaGetSymbolAddress((void**)&t2h, g_t2h); cudaGetSymbolAddress((void**)&t2l, g_t2l);
    cudaGetSymbolAddress((void**)&t3h, g_t3h); cudaGetSymbolAddress((void**)&t3l, g_t3l);
    cudaGetSymbolAddress((void**)&t4h, g_t4h); cudaGetSymbolAddress((void**)&t4l, g_t4l);
    cudaGetSymbolAddress((void**)&w0h, g_w0h); cudaGetSymbolAddress((void**)&w0l, g_w0l);
    cudaGetSymbolAddress((void**)&w1h, g_w1h); cudaGetSymbolAddress((void**)&w1l, g_w1l);
    cudaGetSymbolAddress((void**)&w2h, g_w2h); cudaGetSymbolAddress((void**)&w2l, g_w2l);
    cudaGetSymbolAddress((void**)&x0h, g_tw0h); cudaGetSymbolAddress((void**)&x0l, g_tw0l);
    cudaGetSymbolAddress((void**)&x1h, g_tw1h); cudaGetSymbolAddress((void**)&x1l, g_tw1l);
    cudaGetSymbolAddress((void**)&x2h, g_tw2h); cudaGetSymbolAddress((void**)&x2l, g_tw2l);
    cudaGetSymbolAddress((void**)&x3h, g_tw3h); cudaGetSymbolAddress((void**)&x3l, g_tw3l);

    // ---- fused prepass ----
    conv_all<<<(CONV_TOTAL + 255) / 256, 256>>>(
        x, bw0, bw1, bw2, tw0, tw1, tw2, tw3,
        a0h, a0l,
        w0h, w0l, w1h, w1l, w2h, w2l,
        x0h, x0l, x1h, x1l, x2h, x2l, x3h, x3l);

    const int MB = BATCH / 128;

    // bottom MLP: 13->512->256->128 (relu)
    gemm_hl<<<dim3(4, MB), 256, SMEM_BYTES>>>(a0h, a0l, 32,  w0h, w0l, 32,
                                              bb0, h1h, h1l, nullptr, 512, 32, 1);
    gemm_hl<<<dim3(2, MB), 256, SMEM_BYTES>>>(h1h, h1l, 512, w1h, w1l, 512,
                                              bb1, h2h, h2l, nullptr, 256, 512, 1);
    gemm_hl<<<dim3(1, MB), 256, SMEM_BYTES>>>(h2h, h2l, 256, w2h, w2l, 256,
                                              bb2, nullptr, nullptr, bot, 128, 256, 1);

    // gather + interaction (tensor-core Gram) -> t0 planes [B,512]
    interact_kernel<<<BATCH / 2, 64>>>(x, emb, bot, t0h, t0l);

    // top MLP: 506->1024->1024->512->256 (relu)
    gemm_hl<<<dim3(8, MB), 256, SMEM_BYTES>>>(t0h, t0l, 512,  x0h, x0l, 512,
                                              tb0, t1h, t1l, nullptr, 1024, 512,  1);
    gemm_hl<<<dim3(8, MB), 256, SMEM_BYTES>>>(t1h, t1l, 1024, x1h, x1l, 1024,
                                              tb1, t2h, t2l, nullptr, 1024, 1024, 1);
    gemm_hl<<<dim3(4, MB), 256, SMEM_BYTES>>>(t2h, t2l, 1024, x2h, x2l, 1024,
                                              tb2, t3h, t3l, nullptr, 512,  1024, 1);
    gemm_hl<<<dim3(2, MB), 256, SMEM_BYTES>>>(t3h, t3l, 512,  x3h, x3l, 512,
                                              tb3, t4h, t4l, nullptr, 256,  512,  1);

    // final: 256 -> 1 (no relu)
    final_layer<<<BATCH / 8, 256>>>(t4h, t4l, tw4, tb4, out);
}

// round 15
// speedup vs baseline: 1.1114x; 1.0113x over previous
#include <cuda_runtime.h>
#include <cuda_fp16.h>
#include <cstdint>

// ---------------------------------------------------------------------------
// DLRM forward. GEMMs via mma.sync.m16n8k16.f16, 3-term fp16 split
// (Ah*Bh + Al*Bh + Ah*Bl), fp32 accum (R12 GEMM — at the mma.sync wall).
// R14: tensor-core interact. R15: final 256->1 layer fused into T3's
// epilogue (in-register dot + atomicAdd); out pre-init'd with bias in prepass.
// ---------------------------------------------------------------------------

#define BATCH   16384
#define NDENSE  13
#define NSPARSE 26
#define XCOLS   39
#define EMBDIM  128
#define VOCAB   1000000
#define NFEAT   27

// -------------------- scratch planes (device globals) ----------------------
__device__ __align__(16) uint16_t g_a0h[BATCH * 32],   g_a0l[BATCH * 32];
__device__ __align__(16) uint16_t g_h1h[BATCH * 512],  g_h1l[BATCH * 512];
__device__ __align__(16) uint16_t g_h2h[BATCH * 256],  g_h2l[BATCH * 256];
__device__ __align__(16) float    g_bot[BATCH * 128];
__device__ __align__(16) uint16_t g_t0h[BATCH * 512],  g_t0l[BATCH * 512];
__device__ __align__(16) uint16_t g_t1h[BATCH * 1024], g_t1l[BATCH * 1024];
__device__ __align__(16) uint16_t g_t2h[BATCH * 1024], g_t2l[BATCH * 1024];
__device__ __align__(16) uint16_t g_t3h[BATCH * 512],  g_t3l[BATCH * 512];
// transposed weight planes [N][Kpad]
__device__ __align__(16) uint16_t g_w0h [512  * 32],   g_w0l [512  * 32];
__device__ __align__(16) uint16_t g_w1h [256  * 512],  g_w1l [256  * 512];
__device__ __align__(16) uint16_t g_w2h [128  * 256],  g_w2l [128  * 256];
__device__ __align__(16) uint16_t g_tw0h[1024 * 512],  g_tw0l[1024 * 512];
__device__ __align__(16) uint16_t g_tw1h[1024 * 1024], g_tw1l[1024 * 1024];
__device__ __align__(16) uint16_t g_tw2h[512  * 1024], g_tw2l[512  * 1024];
__device__ __align__(16) uint16_t g_tw3h[256  * 512],  g_tw3l[256  * 512];

// ---------------------------------------------------------------------------
__device__ __forceinline__ void split_h(float v, uint16_t& h, uint16_t& l) {
    __half hh = __float2half_rn(v);
    __half ll = __float2half_rn(v - __half2float(hh));
    h = __half_as_ushort(hh);
    l = __half_as_ushort(ll);
}

__device__ __forceinline__ void mma16(float* c, const uint32_t* a,
                                      uint32_t b0, uint32_t b1) {
    asm volatile(
        "mma.sync.aligned.m16n8k16.row.col.f32.f16.f16.f32 "
        "{%0,%1,%2,%3}, {%4,%5,%6,%7}, {%8,%9}, {%0,%1,%2,%3};\n"
        : "+f"(c[0]), "+f"(c[1]), "+f"(c[2]), "+f"(c[3])
        : "r"(a[0]), "r"(a[1]), "r"(a[2]), "r"(a[3]), "r"(b0), "r"(b1));
}

__device__ __forceinline__ void ldsm4(uint32_t* r, uint32_t addr) {
    asm volatile(
        "ldmatrix.sync.aligned.m8n8.x4.shared.b16 {%0,%1,%2,%3}, [%4];\n"
        : "=r"(r[0]), "=r"(r[1]), "=r"(r[2]), "=r"(r[3]) : "r"(addr));
}

__device__ __forceinline__ void cpa16(uint32_t dst, const void* src) {
    asm volatile("cp.async.cg.shared.global [%0], [%1], 16;\n"
                 :: "r"(dst), "l"(src));
}

// ---------------------------------------------------------------------------
// Fused prepass: split/transpose ALL weights + input to f16 planes, 1 launch.
// Also initializes out[] = tb4[0] (final bias) for the fused dot epilogue.
// ---------------------------------------------------------------------------
__device__ __forceinline__ void seg_conv(const float* __restrict__ in,
                                         uint16_t* __restrict__ oh,
                                         uint16_t* __restrict__ ol,
                                         int j, int K, int Kpad, int N) {
    int n = j / Kpad, k = j - n * Kpad;
    float v = (k < K) ? in[(size_t)k * N + n] : 0.f;
    split_h(v, oh[j], ol[j]);
}

#define CONV_TOTAL 2949120   // 2932736 + 16384 out-init

__global__ void conv_all(const float* __restrict__ x,
    const float* __restrict__ i0, const float* __restrict__ i1,
    const float* __restrict__ i2, const float* __restrict__ i3,
    const float* __restrict__ i4, const float* __restrict__ i5,
    const float* __restrict__ i6,
    uint16_t* a0h, uint16_t* a0l,
    uint16_t* o0h, uint16_t* o0l, uint16_t* o1h, uint16_t* o1l,
    uint16_t* o2h, uint16_t* o2l, uint16_t* o3h, uint16_t* o3l,
    uint16_t* o4h, uint16_t* o4l, uint16_t* o5h, uint16_t* o5l,
    uint16_t* o6h, uint16_t* o6l,
    float* __restrict__ outp, const float* __restrict__ tb4)
{
    int i = blockIdx.x * blockDim.x + threadIdx.x;
    if (i < 524288) {                       // x dense cols -> a0 [B,32]
        int b = i >> 5, k = i & 31;
        float v = (k < NDENSE) ? x[(size_t)b * XCOLS + k] : 0.f;
        split_h(v, a0h[i], a0l[i]);
    }
    else if (i < 540672)  seg_conv(i0, o0h, o0l, i - 524288,  13,   32,   512);
    else if (i < 671744)  seg_conv(i1, o1h, o1l, i - 540672,  512,  512,  256);
    else if (i < 704512)  seg_conv(i2, o2h, o2l, i - 671744,  256,  256,  128);
    else if (i < 1228800) seg_conv(i3, o3h, o3l, i - 704512,  506,  512,  1024);
    else if (i < 2277376) seg_conv(i4, o4h, o4l, i - 1228800, 1024, 1024, 1024);
    else if (i < 2801664) seg_conv(i5, o5h, o5l, i - 2277376, 1024, 1024, 512);
    else if (i < 2932736) seg_conv(i6, o6h, o6l, i - 2801664, 512, 512, 256);
    else if (i < CONV_TOTAL) outp[i - 2932736] = tb4[0];
}

// ---------------------------------------------------------------------------
// GEMM: C[128x128 tile] = act(A @ B^T + bias).
// dot-mode (dotw != nullptr): instead of storing C, compute per-row partial
// dots  sum_col relu(C[row,col])*dotw[col]  and atomicAdd into dout[row].
// ---------------------------------------------------------------------------
#define PADH   40
#define PLANEB 10240
#define BUFB   40960
#define SMEM_BYTES (2 * BUFB)

__global__ __launch_bounds__(256, 2)
void gemm_hl(const uint16_t* __restrict__ Ah, const uint16_t* __restrict__ Al, int lda,
             const uint16_t* __restrict__ Bh, const uint16_t* __restrict__ Bl, int ldb,
             const float* __restrict__ bias,
             uint16_t* __restrict__ Ch, uint16_t* __restrict__ Cl,
             float* __restrict__ Cf, int ldc, int K, int relu,
             const float* __restrict__ dotw, float* __restrict__ dout)
{
    extern __shared__ __align__(16) uint16_t sm[];
    const uint32_t smem_base = (uint32_t)__cvta_generic_to_shared(sm);

    const int tid  = threadIdx.x;
    const int brow = blockIdx.y << 7;
    const int bcol = blockIdx.x << 7;
    const int warp = tid >> 5;
    const int lane = tid & 31;
    const int g    = lane >> 2;
    const int tg   = lane & 3;
    const int wm   = (warp & 3) << 5;
    const int wn   = (warp >> 2) << 6;

    const int r0c = (tid + 0)   >> 2, v0c = (tid + 0)   & 3;
    const int r1c = (tid + 256) >> 2, v1c = (tid + 256) & 3;

    const int lr  = lane & 7;
    const int sel = lane >> 3;
    const int a_row = ((sel & 1) << 3) + lr;
    const int a_kc  = sel >> 1;
    const uint32_t a_base = smem_base + (uint32_t)((wm + a_row) * 80 + a_kc * 16);
    const int b_row = ((sel >> 1) << 3) + lr;
    const int b_kc  = sel & 1;
    const uint32_t b_base = smem_base + 2 * PLANEB +
                            (uint32_t)((wn + b_row) * 80 + b_kc * 16);

    float acc[2][8][4];
#pragma unroll
    for (int mi = 0; mi < 2; mi++)
#pragma unroll
        for (int nj = 0; nj < 8; nj++)
#pragma unroll
            for (int q = 0; q < 4; q++) acc[mi][nj][q] = 0.f;

    const int nst = K >> 5;

    auto issue = [&](int s) {
        const int k0 = s << 5;
        const uint32_t base = smem_base + (uint32_t)(s & 1) * BUFB;
        {
            uint32_t d = base + (uint32_t)(r0c * 80 + v0c * 16);
            size_t ao = (size_t)(brow + r0c) * lda + k0 + v0c * 8;
            size_t bo = (size_t)(bcol + r0c) * ldb + k0 + v0c * 8;
            cpa16(d,              Ah + ao);
            cpa16(d + PLANEB,     Al + ao);
            cpa16(d + 2 * PLANEB, Bh + bo);
            cpa16(d + 3 * PLANEB, Bl + bo);
        }
        {
            uint32_t d = base + (uint32_t)(r1c * 80 + v1c * 16);
            size_t ao = (size_t)(brow + r1c) * lda + k0 + v1c * 8;
            size_t bo = (size_t)(bcol + r1c) * ldb + k0 + v1c * 8;
            cpa16(d,              Ah + ao);
            cpa16(d + PLANEB,     Al + ao);
            cpa16(d + 2 * PLANEB, Bh + bo);
            cpa16(d + 3 * PLANEB, Bl + bo);
        }
        asm volatile("cp.async.commit_group;" ::: "memory");
    };

    issue(0);

    for (int s = 0; s < nst; s++) {
        if (s + 1 < nst) {
            issue(s + 1);
            asm volatile("cp.async.wait_group 1;" ::: "memory");
        } else {
            asm volatile("cp.async.wait_group 0;" ::: "memory");
        }
        __syncthreads();

        const uint32_t buf = (uint32_t)(s & 1) * BUFB;

#pragma unroll
        for (int ks = 0; ks < 2; ks++) {
            const uint32_t ko = buf + (uint32_t)(ks * 32);
            uint32_t ah[2][4], al[2][4];
            ldsm4(ah[0], a_base + ko);
            ldsm4(ah[1], a_base + ko + 1280);
            ldsm4(al[0], a_base + ko + PLANEB);
            ldsm4(al[1], a_base + ko + PLANEB + 1280);
#pragma unroll
            for (int njp = 0; njp < 4; njp++) {
                uint32_t bh[4], bl[4];
                ldsm4(bh, b_base + ko + (uint32_t)(njp * 1280));
                ldsm4(bl, b_base + ko + (uint32_t)(njp * 1280) + PLANEB);
#pragma unroll
                for (int s2 = 0; s2 < 2; s2++) {
                    int nj = (njp << 1) + s2;
#pragma unroll
                    for (int mi = 0; mi < 2; mi++) {
                        mma16(acc[mi][nj], ah[mi], bh[2*s2], bh[2*s2+1]);
                        mma16(acc[mi][nj], al[mi], bh[2*s2], bh[2*s2+1]);
                        mma16(acc[mi][nj], ah[mi], bl[2*s2], bl[2*s2+1]);
                    }
                }
            }
        }
        __syncthreads();
    }

    if (dotw) {
        // ---- fused final layer: per-row dot with dotw, atomicAdd to dout ----
        float p[2][2] = {{0.f, 0.f}, {0.f, 0.f}};
#pragma unroll
        for (int nj = 0; nj < 8; nj++) {
            int col = bcol + wn + (nj << 3) + (tg << 1);
            float b0 = __ldg(&bias[col]), b1 = __ldg(&bias[col + 1]);
            float w0 = __ldg(&dotw[col]), w1 = __ldg(&dotw[col + 1]);
#pragma unroll
            for (int mi = 0; mi < 2; mi++) {
                float v0 = acc[mi][nj][0] + b0;
                float v1 = acc[mi][nj][1] + b1;
                float v2 = acc[mi][nj][2] + b0;
                float v3 = acc[mi][nj][3] + b1;
                if (relu) {
                    v0 = fmaxf(v0, 0.f); v1 = fmaxf(v1, 0.f);
                    v2 = fmaxf(v2, 0.f); v3 = fmaxf(v3, 0.f);
                }
                p[mi][0] = fmaf(v0, w0, fmaf(v1, w1, p[mi][0]));
                p[mi][1] = fmaf(v2, w0, fmaf(v3, w1, p[mi][1]));
            }
        }
#pragma unroll
        for (int mi = 0; mi < 2; mi++)
#pragma unroll
            for (int h = 0; h < 2; h++) {
                float v = p[mi][h];
                v += __shfl_down_sync(0xffffffffu, v, 2);
                v += __shfl_down_sync(0xffffffffu, v, 1);
                if (tg == 0)
                    atomicAdd(&dout[brow + wm + (mi << 4) + g + (h << 3)], v);
            }
        return;
    }

#pragma unroll
    for (int nj = 0; nj < 8; nj++) {
        int col = bcol + wn + (nj << 3) + (tg << 1);
        float b0 = __ldg(&bias[col]), b1 = __ldg(&bias[col + 1]);
#pragma unroll
        for (int mi = 0; mi < 2; mi++) {
            int r0 = brow + wm + (mi << 4) + g;
            float v0 = acc[mi][nj][0] + b0;
            float v1 = acc[mi][nj][1] + b1;
            float v2 = acc[mi][nj][2] + b0;
            float v3 = acc[mi][nj][3] + b1;
            if (relu) {
                v0 = fmaxf(v0, 0.f); v1 = fmaxf(v1, 0.f);
                v2 = fmaxf(v2, 0.f); v3 = fmaxf(v3, 0.f);
            }
            if (Cf) {
                *(float2*)(Cf + (size_t)r0 * ldc + col)       = make_float2(v0, v1);
                *(float2*)(Cf + (size_t)(r0 + 8) * ldc + col) = make_float2(v2, v3);
            } else {
                uint16_t h0, l0, h1x, l1x, h2, l2, h3, l3;
                split_h(v0, h0, l0); split_h(v1, h1x, l1x);
                split_h(v2, h2, l2); split_h(v3, h3, l3);
                *(uint32_t*)(Ch + (size_t)r0 * ldc + col) =
                    (uint32_t)h0 | ((uint32_t)h1x << 16);
                *(uint32_t*)(Cl + (size_t)r0 * ldc + col) =
                    (uint32_t)l0 | ((uint32_t)l1x << 16);
                *(uint32_t*)(Ch + (size_t)(r0 + 8) * ldc + col) =
                    (uint32_t)h2 | ((uint32_t)h3 << 16);
                *(uint32_t*)(Cl + (size_t)(r0 + 8) * ldc + col) =
                    (uint32_t)l2 | ((uint32_t)l3 << 16);
            }
        }
    }
}

// ---------------------------------------------------------------------------
// Fused embedding gather + dot interaction on TENSOR CORES (R14, unchanged).
// ---------------------------------------------------------------------------
#define SROW   136
#define SROWB  272
#define SPLANE (32 * SROW)
#define SPLB   (SPLANE * 2)

__global__ __launch_bounds__(64)
void interact_kernel(const float* __restrict__ x,
                     const float* __restrict__ emb,
                     const float* __restrict__ bot,
                     uint16_t* __restrict__ t0h, uint16_t* __restrict__ t0l)
{
    __shared__ __align__(16) uint16_t fs[2][2 * SPLANE];
    const int warp = threadIdx.x >> 5;
    const int lane = threadIdx.x & 31;
    const int b    = (blockIdx.x << 1) + warp;
    uint16_t* fh = fs[warp];
    uint16_t* fl = fh + SPLANE;
    const uint32_t sbase = (uint32_t)__cvta_generic_to_shared(fh);

    int myidx = 0;
    if (lane < NSPARSE) {
        float c = x[(size_t)b * XCOLS + NDENSE + lane];
        myidx = ((int)c) % VOCAB;
    }

    {
        float4 v = *(const float4*)(bot + (size_t)b * EMBDIM + lane * 4);
        uint16_t hb[4], lb[4];
        split_h(v.x, hb[0], lb[0]); split_h(v.y, hb[1], lb[1]);
        split_h(v.z, hb[2], lb[2]); split_h(v.w, hb[3], lb[3]);
        *(uint2*)&fh[lane * 4] = *(uint2*)hb;
        *(uint2*)&fl[lane * 4] = *(uint2*)lb;
        *(uint2*)(t0h + (size_t)b * 512 + lane * 4) = *(uint2*)hb;
        *(uint2*)(t0l + (size_t)b * 512 + lane * 4) = *(uint2*)lb;
    }
    if (lane < 6) {
        t0h[(size_t)b * 512 + 506 + lane] = 0;
        t0l[(size_t)b * 512 + 506 + lane] = 0;
    }

#pragma unroll
    for (int r = 27; r < 32; r++) {
        *(uint2*)&fh[r * SROW + lane * 4] = make_uint2(0u, 0u);
        *(uint2*)&fl[r * SROW + lane * 4] = make_uint2(0u, 0u);
    }

    for (int j = 0; j < NSPARSE; j++) {
        int row = __shfl_sync(0xffffffffu, myidx, j);
        float4 v = *(const float4*)(emb + (size_t)row * EMBDIM + lane * 4);
        uint16_t hb[4], lb[4];
        split_h(v.x, hb[0], lb[0]); split_h(v.y, hb[1], lb[1]);
        split_h(v.z, hb[2], lb[2]); split_h(v.w, hb[3], lb[3]);
        *(uint2*)&fh[(1 + j) * SROW + lane * 4] = *(uint2*)hb;
        *(uint2*)&fl[(1 + j) * SROW + lane * 4] = *(uint2*)lb;
    }
    __syncwarp();

    const int lr  = lane & 7;
    const int sel = lane >> 3;
    const int a_row = ((sel & 1) << 3) + lr;
    const int a_kc  = sel >> 1;
    const uint32_t a_base = sbase + (uint32_t)(a_row * SROWB + a_kc * 16);
    const int b_row = ((sel >> 1) << 3) + lr;
    const int b_kc  = sel & 1;
    const uint32_t b_base = sbase + (uint32_t)(b_row * SROWB + b_kc * 16);

    float acc[2][4][4];
#pragma unroll
    for (int mi = 0; mi < 2; mi++)
#pragma unroll
        for (int nj = 0; nj < 4; nj++)
#pragma unroll
            for (int q = 0; q < 4; q++) acc[mi][nj][q] = 0.f;

#pragma unroll
    for (int k = 0; k < 8; k++) {
        const uint32_t ko = (uint32_t)(k * 32);
        uint32_t ah[2][4], al[2][4];
        ldsm4(ah[0], a_base + ko);
        ldsm4(ah[1], a_base + ko + 16 * SROWB);
        ldsm4(al[0], a_base + ko + SPLB);
        ldsm4(al[1], a_base + ko + SPLB + 16 * SROWB);
#pragma unroll
        for (int njp = 0; njp < 2; njp++) {
            const uint32_t no = (uint32_t)(njp * 16 * SROWB);
            uint32_t bh[4], bl[4];
            ldsm4(bh, b_base + ko + no);
            ldsm4(bl, b_base + ko + no + SPLB);
#pragma unroll
            for (int s2 = 0; s2 < 2; s2++) {
                int nj = (njp << 1) + s2;
#pragma unroll
                for (int mi = 0; mi < 2; mi++) {
                    mma16(acc[mi][nj], ah[mi], bh[2*s2], bh[2*s2+1]);
                    mma16(acc[mi][nj], al[mi], bh[2*s2], bh[2*s2+1]);
                    mma16(acc[mi][nj], ah[mi], bl[2*s2], bl[2*s2+1]);
                }
            }
        }
    }

    const int g  = lane >> 2;
    const int tg = lane & 3;
    uint16_t* oh = t0h + (size_t)b * 512 + EMBDIM;
    uint16_t* ol = t0l + (size_t)b * 512 + EMBDIM;
#pragma unroll
    for (int mi = 0; mi < 2; mi++)
#pragma unroll
        for (int nj = 0; nj < 4; nj++)
#pragma unroll
            for (int q = 0; q < 4; q++) {
                int i = (mi << 4) + g + ((q & 2) << 2);
                int j = (nj << 3) + (tg << 1) + (q & 1);
                if (i <= j && j < NFEAT) {
                    int off = i * NFEAT - ((i * (i - 1)) >> 1) + (j - i);
                    uint16_t h, l;
                    split_h(acc[mi][nj][q], h, l);
                    oh[off] = h; ol[off] = l;
                }
            }
}

// ---------------------------------------------------------------------------
extern "C" void kernel_launch(void* const* d_in, const int* in_sizes, int n_in,
                              void* d_out, int out_size)
{
    (void)in_sizes; (void)n_in; (void)out_size;

    const float* x   = (const float*)d_in[0];
    const float* bw0 = (const float*)d_in[2];
    const float* bb0 = (const float*)d_in[3];
    const float* bw1 = (const float*)d_in[4];
    const float* bb1 = (const float*)d_in[5];
    const float* bw2 = (const float*)d_in[6];
    const float* bb2 = (const float*)d_in[7];
    const float* emb = (const float*)d_in[8];
    const float* tw0 = (const float*)d_in[9];
    const float* tb0 = (const float*)d_in[10];
    const float* tw1 = (const float*)d_in[11];
    const float* tb1 = (const float*)d_in[12];
    const float* tw2 = (const float*)d_in[13];
    const float* tb2 = (const float*)d_in[14];
    const float* tw3 = (const float*)d_in[15];
    const float* tb3 = (const float*)d_in[16];
    const float* tw4 = (const float*)d_in[17];
    const float* tb4 = (const float*)d_in[18];
    float* out = (float*)d_out;

    cudaFuncSetAttribute(gemm_hl, cudaFuncAttributeMaxDynamicSharedMemorySize,
                         SMEM_BYTES);

    uint16_t *a0h,*a0l,*h1h,*h1l,*h2h,*h2l,*t0h,*t0l,*t1h,*t1l,*t2h,*t2l,*t3h,*t3l;
    uint16_t *w0h,*w0l,*w1h,*w1l,*w2h,*w2l,*x0h,*x0l,*x1h,*x1l,*x2h,*x2l,*x3h,*x3l;
    float *bot;
    cudaGetSymbolAddress((void**)&a0h, g_a0h); cudaGetSymbolAddress((void**)&a0l, g_a0l);
    cudaGetSymbolAddress((void**)&h1h, g_h1h); cudaGetSymbolAddress((void**)&h1l, g_h1l);
    cudaGetSymbolAddress((void**)&h2h, g_h2h); cudaGetSymbolAddress((void**)&h2l, g_h2l);
    cudaGetSymbolAddress((void**)&bot, g_bot);
    cudaGetSymbolAddress((void**)&t0h, g_t0h); cudaGetSymbolAddress((void**)&t0l, g_t0l);
    cudaGetSymbolAddress((void**)&t1h, g_t1h); cudaGetSymbolAddress((void**)&t1l, g_t1l);
    cudaGetSymbolAddress((void**)&t2h, g_t2h); cudaGetSymbolAddress((void**)&t2l, g_t2l);
    cudaGetSymbolAddress((void**)&t3h, g_t3h); cudaGetSymbolAddress((void**)&t3l, g_t3l);
    cudaGetSymbolAddress((void**)&w0h, g_w0h); cudaGetSymbolAddress((void**)&w0l, g_w0l);
    cudaGetSymbolAddress((void**)&w1h, g_w1h); cudaGetSymbolAddress((void**)&w1l, g_w1l);
    cudaGetSymbolAddress((void**)&w2h, g_w2h); cudaGetSymbolAddress((void**)&w2l, g_w2l);
    cudaGetSymbolAddress((void**)&x0h, g_tw0h); cudaGetSymbolAddress((void**)&x0l, g_tw0l);
    cudaGetSymbolAddress((void**)&x1h, g_tw1h); cudaGetSymbolAddress((void**)&x1l, g_tw1l);
    cudaGetSymbolAddress((void**)&x2h, g_tw2h); cudaGetSymbolAddress((void**)&x2l, g_tw2l);
    cudaGetSymbolAddress((void**)&x3h, g_tw3h); cudaGetSymbolAddress((void**)&x3l, g_tw3l);

    // ---- fused prepass (+ out[] = tb4 bias init) ----
    conv_all<<<(CONV_TOTAL + 255) / 256, 256>>>(
        x, bw0, bw1, bw2, tw0, tw1, tw2, tw3,
        a0h, a0l,
        w0h, w0l, w1h, w1l, w2h, w2l,
        x0h, x0l, x1h, x1l, x2h, x2l, x3h, x3l,
        out, tb4);

    const int MB = BATCH / 128;

    // bottom MLP: 13->512->256->128 (relu)
    gemm_hl<<<dim3(4, MB), 256, SMEM_BYTES>>>(a0h, a0l, 32,  w0h, w0l, 32,
        bb0, h1h, h1l, nullptr, 512, 32, 1, nullptr, nullptr);
    gemm_hl<<<dim3(2, MB), 256, SMEM_BYTES>>>(h1h, h1l, 512, w1h, w1l, 512,
        bb1, h2h, h2l, nullptr, 256, 512, 1, nullptr, nullptr);
    gemm_hl<<<dim3(1, MB), 256, SMEM_BYTES>>>(h2h, h2l, 256, w2h, w2l, 256,
        bb2, nullptr, nullptr, bot, 128, 256, 1, nullptr, nullptr);

    // gather + interaction (tensor-core Gram) -> t0 planes [B,512]
    interact_kernel<<<BATCH / 2, 64>>>(x, emb, bot, t0h, t0l);

    // top MLP: 506->1024->1024->512 (relu)
    gemm_hl<<<dim3(8, MB), 256, SMEM_BYTES>>>(t0h, t0l, 512,  x0h, x0l, 512,
        tb0, t1h, t1l, nullptr, 1024, 512,  1, nullptr, nullptr);
    gemm_hl<<<dim3(8, MB), 256, SMEM_BYTES>>>(t1h, t1l, 1024, x1h, x1l, 1024,
        tb1, t2h, t2l, nullptr, 1024, 1024, 1, nullptr, nullptr);
    gemm_hl<<<dim3(4, MB), 256, SMEM_BYTES>>>(t2h, t2l, 1024, x2h, x2l, 1024,
        tb2, t3h, t3l, nullptr, 512,  1024, 1, nullptr, nullptr);

    // T3 (512->256, relu) with fused final 256->1 dot into out (bias pre-init)
    gemm_hl<<<dim3(2, MB), 256, SMEM_BYTES>>>(t3h, t3l, 512,  x3h, x3l, 512,
        tb3, nullptr, nullptr, nullptr, 256, 512, 1, tw4, out);
}